// round 5
// baseline (speedup 1.0000x reference)
#include <cuda_runtime.h>
#include <math.h>

#define C_CH 256
#define OUT_H 7
#define OUT_W 35
#define NLEV 4
#define NSAMP 4                       // 2x2 samples per bin
#define ENTRIES (OUT_W * NLEV * NSAMP)  // 560 sample descriptors per (roi, ph)

// One block handles (roi n, output row ph, channel-chunk of 64).
// 288 threads: precompute phase uses all; main phase uses 280 = 35 pw * 8 channel-groups.
__global__ __launch_bounds__(288, 2)
void rroi_align_fpn_max_kernel(const float* __restrict__ f0,
                               const float* __restrict__ f1,
                               const float* __restrict__ f2,
                               const float* __restrict__ f3,
                               const float* __restrict__ rois,
                               float* __restrict__ out)
{
    __shared__ int4   s_off[ENTRIES];
    __shared__ float4 s_w[ENTRIES];

    const int n   = blockIdx.x;
    const int ph  = blockIdx.y;
    const int tid = threadIdx.x;

    // ---- Phase 1: precompute sample descriptors (channel-independent) ----
    const float r0 = __ldg(rois + n * 6 + 0);   // batch idx
    const float r1 = __ldg(rois + n * 6 + 1);   // cx (image coords)
    const float r2 = __ldg(rois + n * 6 + 2);   // cy
    const float r3 = __ldg(rois + n * 6 + 3);   // w
    const float r4 = __ldg(rois + n * 6 + 4);   // h
    const float r5 = __ldg(rois + n * 6 + 5);   // theta
    float sint, cost;
    sincosf(r5, &sint, &cost);
    const int b = (int)r0;

    for (int e = tid; e < ENTRIES; e += blockDim.x) {
        // layout: ent = (lev*4 + s)*35 + pw   (pw minor -> conflict-free LDS.128)
        const int pw  = e % OUT_W;
        const int q   = e / OUT_W;       // 0..15
        const int lev = q >> 2;
        const int s   = q & 3;
        const int sy  = s >> 1;
        const int sx  = s & 1;

        const float sc = 0.25f / (float)(1 << lev);   // 1/4, 1/8, 1/16, 1/32
        const int   Hc = 256 >> lev;
        const int   Wc = Hc;
        const int   HW = Hc * Wc;

        const float cx = r1 * sc;
        const float cy = r2 * sc;
        const float w  = fmaxf(r3 * sc, 1.0f);
        const float h  = fmaxf(r4 * sc, 1.0f);
        const float bin_h = h * (1.0f / OUT_H);
        const float bin_w = w * (1.0f / OUT_W);

        const float gy = (float)ph + ((float)sy + 0.5f) * 0.5f;
        const float gx = (float)pw + ((float)sx + 0.5f) * 0.5f;
        const float yy = gy * bin_h - 0.5f * h;
        const float xx = gx * bin_w - 0.5f * w;

        float x = xx * cost - yy * sint + cx;
        float y = xx * sint + yy * cost + cy;

        const float Hf = (float)Hc, Wf = (float)Wc;
        const bool valid = (y >= -1.0f) && (y <= Hf) && (x >= -1.0f) && (x <= Wf);
        y = fminf(fmaxf(y, 0.0f), Hf - 1.0f);
        x = fminf(fmaxf(x, 0.0f), Wf - 1.0f);

        const int y0 = (int)floorf(y);
        const int x0 = (int)floorf(x);
        const int y1 = min(y0 + 1, Hc - 1);
        const int x1 = min(x0 + 1, Wc - 1);
        const float ly = y - (float)y0;
        const float lx = x - (float)x0;
        const float hy = 1.0f - ly;
        const float hx = 1.0f - lx;
        const float qv = valid ? 0.25f : 0.0f;   // fold 1/(ns*ns) mean + validity

        const int base = b * C_CH * HW;          // batch offset, channel 0
        s_off[e] = make_int4(base + y0 * Wc + x0,
                             base + y0 * Wc + x1,
                             base + y1 * Wc + x0,
                             base + y1 * Wc + x1);
        s_w[e]   = make_float4(hy * hx * qv, hy * lx * qv,
                               ly * hx * qv, ly * lx * qv);
    }
    __syncthreads();

    // ---- Phase 2: gather + bilinear + max over levels ----
    if (tid >= OUT_W * 8) return;                // 280 workers
    const int pw    = tid % OUT_W;
    const int cs    = tid / OUT_W;               // 0..7
    const int cbase = blockIdx.z * 64 + cs * 8;  // this thread's 8 channels

    const float* const feats[NLEV] = {f0, f1, f2, f3};
    const int HWs[NLEV] = {256 * 256, 128 * 128, 64 * 64, 32 * 32};

    float acc[8];
    #pragma unroll
    for (int lev = 0; lev < NLEV; ++lev) {
        const int HW = HWs[lev];
        const float* __restrict__ fb = feats[lev] + cbase * HW;
        const int eb = lev * 4 * OUT_W + pw;
        const int4   o0 = s_off[eb];
        const int4   o1 = s_off[eb + OUT_W];
        const int4   o2 = s_off[eb + 2 * OUT_W];
        const int4   o3 = s_off[eb + 3 * OUT_W];
        const float4 w0 = s_w[eb];
        const float4 w1 = s_w[eb + OUT_W];
        const float4 w2 = s_w[eb + 2 * OUT_W];
        const float4 w3 = s_w[eb + 3 * OUT_W];

        #pragma unroll
        for (int j = 0; j < 8; ++j) {
            const float* __restrict__ fc = fb + j * HW;
            float v;
            v = w0.x * __ldg(fc + o0.x);
            v = fmaf(w0.y, __ldg(fc + o0.y), v);
            v = fmaf(w0.z, __ldg(fc + o0.z), v);
            v = fmaf(w0.w, __ldg(fc + o0.w), v);
            v = fmaf(w1.x, __ldg(fc + o1.x), v);
            v = fmaf(w1.y, __ldg(fc + o1.y), v);
            v = fmaf(w1.z, __ldg(fc + o1.z), v);
            v = fmaf(w1.w, __ldg(fc + o1.w), v);
            v = fmaf(w2.x, __ldg(fc + o2.x), v);
            v = fmaf(w2.y, __ldg(fc + o2.y), v);
            v = fmaf(w2.z, __ldg(fc + o2.z), v);
            v = fmaf(w2.w, __ldg(fc + o2.w), v);
            v = fmaf(w3.x, __ldg(fc + o3.x), v);
            v = fmaf(w3.y, __ldg(fc + o3.y), v);
            v = fmaf(w3.z, __ldg(fc + o3.z), v);
            v = fmaf(w3.w, __ldg(fc + o3.w), v);
            acc[j] = (lev == 0) ? v : fmaxf(acc[j], v);
        }
    }

    // out[n][c][ph][pw], c = cbase + j  -> stride 245 per j
    float* op = out + (((size_t)n * C_CH + cbase) * OUT_H + ph) * OUT_W + pw;
    #pragma unroll
    for (int j = 0; j < 8; ++j)
        op[(size_t)j * (OUT_H * OUT_W)] = acc[j];
}

extern "C" void kernel_launch(void* const* d_in, const int* in_sizes, int n_in,
                              void* d_out, int out_size)
{
    const float* f0   = (const float*)d_in[0];
    const float* f1   = (const float*)d_in[1];
    const float* f2   = (const float*)d_in[2];
    const float* f3   = (const float*)d_in[3];
    const float* rois = (const float*)d_in[4];
    float* out = (float*)d_out;

    const int N = in_sizes[4] / 6;   // number of rois

    dim3 grid(N, OUT_H, 4);          // 4 chunks of 64 channels
    dim3 block(288);
    rroi_align_fpn_max_kernel<<<grid, block>>>(f0, f1, f2, f3, rois, out);
}

// round 6
// speedup vs baseline: 1.3870x; 1.3870x over previous
#include <cuda_runtime.h>
#include <math.h>

#define C_CH  256
#define OUT_H 7
#define OUT_W 35

// Gather + bilinear for 4 consecutive channels at one level (HW compile-time).
// off[] already contains batch-base + pixel offset (channel 0).
template<int HW>
__device__ __forceinline__ void level_acc(const float* __restrict__ fb,
                                          const int* __restrict__ off,
                                          const float* __restrict__ wt,
                                          float v[4])
{
    #pragma unroll
    for (int j = 0; j < 4; ++j) {
        const float* __restrict__ fc = fb + j * HW;
        float t;
        t = wt[0] * __ldg(fc + off[0]);
        t = fmaf(wt[1], __ldg(fc + off[1]), t);
        t = fmaf(wt[2], __ldg(fc + off[2]), t);
        t = fmaf(wt[3], __ldg(fc + off[3]), t);
        v[j] = t;
    }
}

// Block = (roi n, output row ph). 160 threads = 5 warps.
// Lane mapping: warp w covers pw in [8w, 8w+8); lane = pw_local*4 + s,
// where s = sub-sample index (sy = s>>1, sx = s&1). A warp's gather footprint
// is 8 bins wide (vs 32 before), collapsing L1 wavefront replays.
__global__ __launch_bounds__(160, 6)
void rroi_align_fpn_max_kernel(const float* __restrict__ f0,
                               const float* __restrict__ f1,
                               const float* __restrict__ f2,
                               const float* __restrict__ f3,
                               const float* __restrict__ rois,
                               float* __restrict__ out)
{
    const int n    = blockIdx.x;
    const int ph   = blockIdx.y;
    const int tid  = threadIdx.x;
    const int lane = tid & 31;
    const int wrp  = tid >> 5;
    const int pw   = wrp * 8 + (lane >> 2);   // 0..39 (35..39 are dummy lanes)
    const int s    = lane & 3;
    const int sy   = s >> 1;
    const int sx   = s & 1;

    // ---- Per-lane descriptor computation (registers only) ----
    const float r1 = __ldg(rois + n * 6 + 1);   // cx (image coords)
    const float r2 = __ldg(rois + n * 6 + 2);   // cy
    const float r3 = __ldg(rois + n * 6 + 3);   // w
    const float r4 = __ldg(rois + n * 6 + 4);   // h
    const float r5 = __ldg(rois + n * 6 + 5);   // theta
    const int   b  = (int)__ldg(rois + n * 6 + 0);
    float sint, cost;
    sincosf(r5, &sint, &cost);

    int   off[4][4];
    float wt[4][4];

    #pragma unroll
    for (int lev = 0; lev < 4; ++lev) {
        const int   Hc = 256 >> lev;
        const int   HW = Hc * Hc;
        const float sc = 0.25f / (float)(1 << lev);

        const float cx = r1 * sc;
        const float cy = r2 * sc;
        const float w  = fmaxf(r3 * sc, 1.0f);
        const float h  = fmaxf(r4 * sc, 1.0f);

        const float gy = (float)ph + ((float)sy + 0.5f) * 0.5f;
        const float gx = (float)pw + ((float)sx + 0.5f) * 0.5f;
        const float yy = gy * (h * (1.0f / OUT_H)) - 0.5f * h;
        const float xx = gx * (w * (1.0f / OUT_W)) - 0.5f * w;

        float x = xx * cost - yy * sint + cx;
        float y = xx * sint + yy * cost + cy;

        const float Hf = (float)Hc;
        const bool valid = (y >= -1.0f) && (y <= Hf) && (x >= -1.0f) && (x <= Hf);
        y = fminf(fmaxf(y, 0.0f), Hf - 1.0f);
        x = fminf(fmaxf(x, 0.0f), Hf - 1.0f);

        const int y0 = (int)floorf(y);
        const int x0 = (int)floorf(x);
        const int y1 = min(y0 + 1, Hc - 1);
        const int x1 = min(x0 + 1, Hc - 1);
        const float ly = y - (float)y0;
        const float lx = x - (float)x0;
        const float hy = 1.0f - ly;
        const float hx = 1.0f - lx;
        const float qv = valid ? 0.25f : 0.0f;   // fold 2x2 mean + validity

        const int base = b * C_CH * HW;          // batch offset, channel 0
        off[lev][0] = base + y0 * Hc + x0;
        off[lev][1] = base + y0 * Hc + x1;
        off[lev][2] = base + y1 * Hc + x0;
        off[lev][3] = base + y1 * Hc + x1;
        wt[lev][0]  = hy * hx * qv;
        wt[lev][1]  = hy * lx * qv;
        wt[lev][2]  = ly * hx * qv;
        wt[lev][3]  = ly * lx * qv;
    }

    const bool writer = (s == 0) && (pw < OUT_W);
    float* __restrict__ op =
        out + ((size_t)n * C_CH * (OUT_H * OUT_W)) + ph * OUT_W + pw;

    // ---- Channel loop: 4 channels per iteration ----
    for (int c = 0; c < C_CH; c += 4) {
        float v0[4], v1[4], v2[4], v3[4];
        level_acc<256 * 256>(f0 + c * (256 * 256), off[0], wt[0], v0);
        level_acc<128 * 128>(f1 + c * (128 * 128), off[1], wt[1], v1);
        level_acc< 64 *  64>(f2 + c * ( 64 *  64), off[2], wt[2], v2);
        level_acc< 32 *  32>(f3 + c * ( 32 *  32), off[3], wt[3], v3);

        #pragma unroll
        for (int j = 0; j < 4; ++j) {
            float a0 = v0[j], a1 = v1[j], a2 = v2[j], a3 = v3[j];
            // sum the 4 sample lanes (lanes {pw_loc*4 .. +3}) per level
            a0 += __shfl_xor_sync(0xffffffffu, a0, 1);
            a1 += __shfl_xor_sync(0xffffffffu, a1, 1);
            a2 += __shfl_xor_sync(0xffffffffu, a2, 1);
            a3 += __shfl_xor_sync(0xffffffffu, a3, 1);
            a0 += __shfl_xor_sync(0xffffffffu, a0, 2);
            a1 += __shfl_xor_sync(0xffffffffu, a1, 2);
            a2 += __shfl_xor_sync(0xffffffffu, a2, 2);
            a3 += __shfl_xor_sync(0xffffffffu, a3, 2);
            const float m = fmaxf(fmaxf(a0, a1), fmaxf(a2, a3));
            if (writer)
                op[(size_t)(c + j) * (OUT_H * OUT_W)] = m;
        }
    }
}

extern "C" void kernel_launch(void* const* d_in, const int* in_sizes, int n_in,
                              void* d_out, int out_size)
{
    const float* f0   = (const float*)d_in[0];
    const float* f1   = (const float*)d_in[1];
    const float* f2   = (const float*)d_in[2];
    const float* f3   = (const float*)d_in[3];
    const float* rois = (const float*)d_in[4];
    float* out = (float*)d_out;

    const int N = in_sizes[4] / 6;

    dim3 grid(N, OUT_H);
    dim3 block(160);
    rroi_align_fpn_max_kernel<<<grid, block>>>(f0, f1, f2, f3, rois, out);
}

// round 7
// speedup vs baseline: 3.2583x; 2.3492x over previous
#include <cuda_runtime.h>
#include <math.h>

#define C_CH  256
#define OUT_H 7
#define OUT_W 35
#define ENTRIES (OUT_W * 4 * 4)   // 560 descriptors per (roi, ph)

// -------- channel-last scratch buffers (static: allocation-free) --------
__device__ float g_t0[(size_t)2 * 256 * 256 * 256];  // [B][256*256][C] 134MB
__device__ float g_t1[(size_t)2 * 256 * 128 * 128];  // 33.5MB
__device__ float g_t2[(size_t)2 * 256 *  64 *  64];  // 8.4MB
__device__ float g_t3[(size_t)2 * 256 *  32 *  32];  // 2.1MB

// -------- NCHW -> NHWC transpose, 32x32 smem tile --------
__global__ __launch_bounds__(256)
void transpose_kernel(const float* __restrict__ in, int HW, int lev)
{
    __shared__ float tile[32][33];
    float* __restrict__ outp = (lev == 0) ? g_t0 : (lev == 1) ? g_t1
                             : (lev == 2) ? g_t2 : g_t3;
    const int b  = blockIdx.z;
    const int c0 = blockIdx.y * 32;
    const int p0 = blockIdx.x * 32;
    const int tx = threadIdx.x, ty = threadIdx.y;

    const float* __restrict__ ip = in + ((size_t)b * C_CH + c0) * HW + p0;
    #pragma unroll
    for (int k = 0; k < 4; ++k)
        tile[ty + 8 * k][tx] = __ldg(ip + (size_t)(ty + 8 * k) * HW + tx);
    __syncthreads();
    float* __restrict__ op = outp + ((size_t)b * HW + p0) * C_CH + c0;
    #pragma unroll
    for (int k = 0; k < 4; ++k)
        op[(size_t)(ty + 8 * k) * C_CH + tx] = tile[tx][ty + 8 * k];
}

__device__ __forceinline__ float4 max4(float4 a, float4 b)
{
    return make_float4(fmaxf(a.x, b.x), fmaxf(a.y, b.y),
                       fmaxf(a.z, b.z), fmaxf(a.w, b.w));
}

// -------- main kernel: block = (roi n, row ph), 320 threads --------
// tid&63  = cg  (channels c = cg*4 .. cg*4+3, lane-owned float4)
// tid>>6  = pw_par in [0,5); thread handles pw = pw_par*7 + i, i in [0,7)
__global__ __launch_bounds__(320, 2)
void rroi_main_kernel(const float* __restrict__ rois, float* __restrict__ out)
{
    __shared__ int4   s_pix[ENTRIES];       // 4 tap pixel indices (b*HW + y*W + x)
    __shared__ float4 s_wt[ENTRIES];        // 4 premultiplied tap weights
    __shared__ float  s_out[35 * 128];      // one 128-channel half of the row

    const int n   = blockIdx.x;
    const int ph  = blockIdx.y;
    const int tid = threadIdx.x;
    const int cg  = tid & 63;
    const int pwp = tid >> 6;

    // ---- Phase 1: descriptors (channel-independent) ----
    const float r1 = __ldg(rois + n * 6 + 1);
    const float r2 = __ldg(rois + n * 6 + 2);
    const float r3 = __ldg(rois + n * 6 + 3);
    const float r4 = __ldg(rois + n * 6 + 4);
    const float r5 = __ldg(rois + n * 6 + 5);
    const int   b  = (int)__ldg(rois + n * 6 + 0);
    float sint, cost;
    sincosf(r5, &sint, &cost);

    for (int e = tid; e < ENTRIES; e += 320) {
        const int pw  = e % OUT_W;
        const int q   = e / OUT_W;          // 0..15
        const int lev = q >> 2;
        const int s   = q & 3;
        const int sy  = s >> 1;
        const int sx  = s & 1;

        const int   Hc = 256 >> lev;
        const int   HW = Hc * Hc;
        const float sc = 0.25f / (float)(1 << lev);

        const float cx = r1 * sc;
        const float cy = r2 * sc;
        const float w  = fmaxf(r3 * sc, 1.0f);
        const float h  = fmaxf(r4 * sc, 1.0f);

        const float gy = (float)ph + ((float)sy + 0.5f) * 0.5f;
        const float gx = (float)pw + ((float)sx + 0.5f) * 0.5f;
        const float yy = gy * (h * (1.0f / OUT_H)) - 0.5f * h;
        const float xx = gx * (w * (1.0f / OUT_W)) - 0.5f * w;

        float x = xx * cost - yy * sint + cx;
        float y = xx * sint + yy * cost + cy;

        const float Hf = (float)Hc;
        const bool valid = (y >= -1.0f) && (y <= Hf) && (x >= -1.0f) && (x <= Hf);
        y = fminf(fmaxf(y, 0.0f), Hf - 1.0f);
        x = fminf(fmaxf(x, 0.0f), Hf - 1.0f);

        const int y0 = (int)floorf(y);
        const int x0 = (int)floorf(x);
        const int y1 = min(y0 + 1, Hc - 1);
        const int x1 = min(x0 + 1, Hc - 1);
        const float ly = y - (float)y0;
        const float lx = x - (float)x0;
        const float hy = 1.0f - ly;
        const float hx = 1.0f - lx;
        const float qv = valid ? 0.25f : 0.0f;

        const int base = b * HW;
        s_pix[e] = make_int4(base + y0 * Hc + x0, base + y0 * Hc + x1,
                             base + y1 * Hc + x0, base + y1 * Hc + x1);
        s_wt[e]  = make_float4(hy * hx * qv, hy * lx * qv,
                               ly * hx * qv, ly * lx * qv);
    }
    __syncthreads();

    // ---- Phase 2: coalesced channel-last gathers ----
    const float4* __restrict__ T0 = (const float4*)g_t0;
    const float4* __restrict__ T1 = (const float4*)g_t1;
    const float4* __restrict__ T2 = (const float4*)g_t2;
    const float4* __restrict__ T3 = (const float4*)g_t3;

    float4 best[7];
    #pragma unroll
    for (int i = 0; i < 7; ++i) {
        const int pw = pwp * 7 + i;
        float4 bi;
        #pragma unroll
        for (int lev = 0; lev < 4; ++lev) {
            const float4* __restrict__ T =
                (lev == 0) ? T0 : (lev == 1) ? T1 : (lev == 2) ? T2 : T3;
            float4 a = make_float4(0.f, 0.f, 0.f, 0.f);
            #pragma unroll
            for (int s = 0; s < 4; ++s) {
                const int e = (lev * 4 + s) * OUT_W + pw;
                const int4   p = s_pix[e];
                const float4 w = s_wt[e];
                float4 v;
                v = __ldg(T + ((size_t)p.x * 64 + cg));
                a.x = fmaf(w.x, v.x, a.x); a.y = fmaf(w.x, v.y, a.y);
                a.z = fmaf(w.x, v.z, a.z); a.w = fmaf(w.x, v.w, a.w);
                v = __ldg(T + ((size_t)p.y * 64 + cg));
                a.x = fmaf(w.y, v.x, a.x); a.y = fmaf(w.y, v.y, a.y);
                a.z = fmaf(w.y, v.z, a.z); a.w = fmaf(w.y, v.w, a.w);
                v = __ldg(T + ((size_t)p.z * 64 + cg));
                a.x = fmaf(w.z, v.x, a.x); a.y = fmaf(w.z, v.y, a.y);
                a.z = fmaf(w.z, v.z, a.z); a.w = fmaf(w.z, v.w, a.w);
                v = __ldg(T + ((size_t)p.w * 64 + cg));
                a.x = fmaf(w.w, v.x, a.x); a.y = fmaf(w.w, v.y, a.y);
                a.z = fmaf(w.w, v.z, a.z); a.w = fmaf(w.w, v.w, a.w);
            }
            bi = (lev == 0) ? a : max4(bi, a);
        }
        best[i] = bi;
    }

    // ---- Phase 3: stage through smem in 2 halves, write near-coalesced ----
    #pragma unroll
    for (int h = 0; h < 2; ++h) {
        __syncthreads();
        if ((cg >> 5) == h) {
            const int cl = (cg & 31) * 4;   // 0..124
            #pragma unroll
            for (int i = 0; i < 7; ++i) {
                const int pw = pwp * 7 + i;
                s_out[(cl + 0) * OUT_W + pw] = best[i].x;
                s_out[(cl + 1) * OUT_W + pw] = best[i].y;
                s_out[(cl + 2) * OUT_W + pw] = best[i].z;
                s_out[(cl + 3) * OUT_W + pw] = best[i].w;
            }
        }
        __syncthreads();
        float* __restrict__ ob =
            out + (((size_t)n * C_CH + h * 128) * OUT_H + ph) * OUT_W;
        for (int idx = tid; idx < 128 * OUT_W; idx += 320) {
            const int cl = idx / OUT_W;
            const int pw = idx - cl * OUT_W;
            ob[cl * (OUT_H * OUT_W) + pw] = s_out[idx];
        }
    }
}

extern "C" void kernel_launch(void* const* d_in, const int* in_sizes, int n_in,
                              void* d_out, int out_size)
{
    const float* f0   = (const float*)d_in[0];
    const float* f1   = (const float*)d_in[1];
    const float* f2   = (const float*)d_in[2];
    const float* f3   = (const float*)d_in[3];
    const float* rois = (const float*)d_in[4];
    float* out = (float*)d_out;

    const int N = in_sizes[4] / 6;

    dim3 tb(32, 8);
    transpose_kernel<<<dim3(256 * 256 / 32, C_CH / 32, 2), tb>>>(f0, 256 * 256, 0);
    transpose_kernel<<<dim3(128 * 128 / 32, C_CH / 32, 2), tb>>>(f1, 128 * 128, 1);
    transpose_kernel<<<dim3( 64 *  64 / 32, C_CH / 32, 2), tb>>>(f2,  64 *  64, 2);
    transpose_kernel<<<dim3( 32 *  32 / 32, C_CH / 32, 2), tb>>>(f3,  32 *  32, 3);

    rroi_main_kernel<<<dim3(N, OUT_H), 320>>>(rois, out);
}

// round 8
// speedup vs baseline: 5.3279x; 1.6352x over previous
#include <cuda_runtime.h>
#include <cuda_fp16.h>
#include <math.h>

#define C_CH  256
#define OUT_H 7
#define OUT_W 35
#define ENTRIES (OUT_W * 4 * 4)   // 560 descriptors per (roi, ph)

// -------- channel-last fp16 scratch (static: allocation-free) --------
__device__ __half g_h0[(size_t)2 * 256 * 256 * 256];  // 67MB
__device__ __half g_h1[(size_t)2 * 256 * 128 * 128];  // 16.8MB
__device__ __half g_h2[(size_t)2 * 256 *  64 *  64];  // 4.2MB
__device__ __half g_h3[(size_t)2 * 256 *  32 *  32];  // 1.05MB

// -------- NCHW fp32 -> NHWC fp16 transpose, 64ch x 32pix tile --------
__global__ __launch_bounds__(256)
void transpose_kernel(const float* __restrict__ in, int HW, int lev)
{
    __shared__ float tile[64][33];
    __half* __restrict__ outp = (lev == 0) ? g_h0 : (lev == 1) ? g_h1
                              : (lev == 2) ? g_h2 : g_h3;
    const int b  = blockIdx.z;
    const int c0 = blockIdx.y * 64;
    const int p0 = blockIdx.x * 32;
    const int tx = threadIdx.x;          // pix within tile (read phase)
    const int ty = threadIdx.y;

    const float* __restrict__ ip = in + ((size_t)b * C_CH + c0) * HW + p0;
    #pragma unroll
    for (int k = 0; k < 8; ++k) {
        const int c = ty + 8 * k;        // 0..63
        tile[c][tx] = __ldg(ip + (size_t)c * HW + tx);
    }
    __syncthreads();

    // write: 32 lanes x half2 (2 ch) = 128B per row
    const int tid = ty * 32 + tx;
    const int cl  = tid & 31;            // channel pair
    const int r   = tid >> 5;            // 0..7
    __half2* __restrict__ op =
        (__half2*)(outp + ((size_t)b * HW + p0) * C_CH + c0) + cl;
    #pragma unroll
    for (int m = 0; m < 4; ++m) {
        const int pix = r + 8 * m;
        op[(size_t)pix * (C_CH / 2)] =
            __floats2half2_rn(tile[2 * cl][pix], tile[2 * cl + 1][pix]);
    }
}

// One fp16 tap: 32 lanes x LDG.128 -> 256 channels; fp32 accumulate.
__device__ __forceinline__ void tap(const float4* __restrict__ T,
                                    int p, float w, int lane, float acc[8])
{
    const float4 r = __ldg(T + ((size_t)p * 32 + lane));
    float2 f;
    f = __half22float2(*(const __half2*)&r.x);
    acc[0] = fmaf(w, f.x, acc[0]); acc[1] = fmaf(w, f.y, acc[1]);
    f = __half22float2(*(const __half2*)&r.y);
    acc[2] = fmaf(w, f.x, acc[2]); acc[3] = fmaf(w, f.y, acc[3]);
    f = __half22float2(*(const __half2*)&r.z);
    acc[4] = fmaf(w, f.x, acc[4]); acc[5] = fmaf(w, f.y, acc[5]);
    f = __half22float2(*(const __half2*)&r.w);
    acc[6] = fmaf(w, f.x, acc[6]); acc[7] = fmaf(w, f.y, acc[7]);
}

// -------- main kernel: block = (roi n, row ph), 256 threads = 8 warps --------
// warp w handles pw = w, w+8, w+16, w+24, w+32 (<35); lane owns 8 channels.
__global__ __launch_bounds__(256)
void rroi_main_kernel(const float* __restrict__ rois, float* __restrict__ out)
{
    __shared__ int4   s_pix[ENTRIES];
    __shared__ float4 s_wt[ENTRIES];
    __shared__ float  s_out[OUT_W * 257];   // [pw][c], pad 257

    const int n    = blockIdx.x;
    const int ph   = blockIdx.y;
    const int tid  = threadIdx.x;
    const int lane = tid & 31;
    const int wrp  = tid >> 5;

    // ---- Phase 1: descriptors (channel-independent) ----
    const float r1 = __ldg(rois + n * 6 + 1);
    const float r2 = __ldg(rois + n * 6 + 2);
    const float r3 = __ldg(rois + n * 6 + 3);
    const float r4 = __ldg(rois + n * 6 + 4);
    const float r5 = __ldg(rois + n * 6 + 5);
    const int   b  = (int)__ldg(rois + n * 6 + 0);
    float sint, cost;
    sincosf(r5, &sint, &cost);

    for (int e = tid; e < ENTRIES; e += 256) {
        const int pw  = e % OUT_W;
        const int q   = e / OUT_W;
        const int lev = q >> 2;
        const int s   = q & 3;
        const int sy  = s >> 1;
        const int sx  = s & 1;

        const int   Hc = 256 >> lev;
        const int   HW = Hc * Hc;
        const float sc = 0.25f / (float)(1 << lev);

        const float cx = r1 * sc;
        const float cy = r2 * sc;
        const float w  = fmaxf(r3 * sc, 1.0f);
        const float h  = fmaxf(r4 * sc, 1.0f);

        const float gy = (float)ph + ((float)sy + 0.5f) * 0.5f;
        const float gx = (float)pw + ((float)sx + 0.5f) * 0.5f;
        const float yy = gy * (h * (1.0f / OUT_H)) - 0.5f * h;
        const float xx = gx * (w * (1.0f / OUT_W)) - 0.5f * w;

        float x = xx * cost - yy * sint + cx;
        float y = xx * sint + yy * cost + cy;

        const float Hf = (float)Hc;
        const bool valid = (y >= -1.0f) && (y <= Hf) && (x >= -1.0f) && (x <= Hf);
        y = fminf(fmaxf(y, 0.0f), Hf - 1.0f);
        x = fminf(fmaxf(x, 0.0f), Hf - 1.0f);

        const int y0 = (int)floorf(y);
        const int x0 = (int)floorf(x);
        const int y1 = min(y0 + 1, Hc - 1);
        const int x1 = min(x0 + 1, Hc - 1);
        const float ly = y - (float)y0;
        const float lx = x - (float)x0;
        const float hy = 1.0f - ly;
        const float hx = 1.0f - lx;
        const float qv = valid ? 0.25f : 0.0f;

        const int base = b * HW;
        s_pix[e] = make_int4(base + y0 * Hc + x0, base + y0 * Hc + x1,
                             base + y1 * Hc + x0, base + y1 * Hc + x1);
        s_wt[e]  = make_float4(hy * hx * qv, hy * lx * qv,
                               ly * hx * qv, ly * lx * qv);
    }
    __syncthreads();

    const float4* __restrict__ T0 = (const float4*)g_h0;
    const float4* __restrict__ T1 = (const float4*)g_h1;
    const float4* __restrict__ T2 = (const float4*)g_h2;
    const float4* __restrict__ T3 = (const float4*)g_h3;

    // ---- Phase 2: gathers ----
    #pragma unroll
    for (int pwi = 0; pwi < 5; ++pwi) {
        const int pw = wrp + 8 * pwi;
        if (pw < OUT_W) {
            float best[8];
            #pragma unroll
            for (int lev = 0; lev < 4; ++lev) {
                const float4* __restrict__ T =
                    (lev == 0) ? T0 : (lev == 1) ? T1 : (lev == 2) ? T2 : T3;
                float acc[8] = {0.f, 0.f, 0.f, 0.f, 0.f, 0.f, 0.f, 0.f};
                #pragma unroll
                for (int s = 0; s < 4; ++s) {
                    const int e = (lev * 4 + s) * OUT_W + pw;
                    const int4   p = s_pix[e];
                    const float4 w = s_wt[e];
                    tap(T, p.x, w.x, lane, acc);
                    tap(T, p.y, w.y, lane, acc);
                    tap(T, p.z, w.z, lane, acc);
                    tap(T, p.w, w.w, lane, acc);
                }
                #pragma unroll
                for (int j = 0; j < 8; ++j)
                    best[j] = (lev == 0) ? acc[j] : fmaxf(best[j], acc[j]);
            }
            #pragma unroll
            for (int j = 0; j < 8; ++j)
                s_out[pw * 257 + lane * 8 + j] = best[j];
        }
    }
    __syncthreads();

    // ---- Phase 3: coalesced output write ----
    float* __restrict__ ob = out + (((size_t)n * C_CH) * OUT_H + ph) * OUT_W;
    for (int idx = tid; idx < C_CH * OUT_W; idx += 256) {
        const int c  = idx / OUT_W;
        const int pw = idx - c * OUT_W;
        ob[(size_t)c * (OUT_H * OUT_W) + pw] = s_out[pw * 257 + c];
    }
}

extern "C" void kernel_launch(void* const* d_in, const int* in_sizes, int n_in,
                              void* d_out, int out_size)
{
    const float* f0   = (const float*)d_in[0];
    const float* f1   = (const float*)d_in[1];
    const float* f2   = (const float*)d_in[2];
    const float* f3   = (const float*)d_in[3];
    const float* rois = (const float*)d_in[4];
    float* out = (float*)d_out;

    const int N = in_sizes[4] / 6;

    dim3 tb(32, 8);
    transpose_kernel<<<dim3(256 * 256 / 32, C_CH / 64, 2), tb>>>(f0, 256 * 256, 0);
    transpose_kernel<<<dim3(128 * 128 / 32, C_CH / 64, 2), tb>>>(f1, 128 * 128, 1);
    transpose_kernel<<<dim3( 64 *  64 / 32, C_CH / 64, 2), tb>>>(f2,  64 *  64, 2);
    transpose_kernel<<<dim3( 32 *  32 / 32, C_CH / 64, 2), tb>>>(f3,  32 *  32, 3);

    rroi_main_kernel<<<dim3(N, OUT_H), 256>>>(rois, out);
}

// round 10
// speedup vs baseline: 5.4693x; 1.0265x over previous
#include <cuda_runtime.h>
#include <cuda_fp16.h>
#include <stdint.h>
#include <math.h>

#define C_CH  256
#define OUT_H 7
#define OUT_W 35
#define ENTRIES (OUT_W * 4 * 4)   // 560 descriptors per (roi, ph)

// -------- channel-last fp16 scratch (static: allocation-free) --------
__device__ __half g_h0[(size_t)2 * 256 * 256 * 256];  // 67MB
__device__ __half g_h1[(size_t)2 * 256 * 128 * 128];  // 16.8MB
__device__ __half g_h2[(size_t)2 * 256 *  64 *  64];  // 4.2MB
__device__ __half g_h3[(size_t)2 * 256 *  32 *  32];  // 1.05MB

// -------- NCHW fp32 -> NHWC fp16 transpose, 64ch x 32pix tile --------
__global__ __launch_bounds__(256)
void transpose_kernel(const float* __restrict__ in, int HW, int lev)
{
    __shared__ float tile[64][33];
    __half* __restrict__ outp = (lev == 0) ? g_h0 : (lev == 1) ? g_h1
                              : (lev == 2) ? g_h2 : g_h3;
    const int b  = blockIdx.z;
    const int c0 = blockIdx.y * 64;
    const int p0 = blockIdx.x * 32;
    const int tx = threadIdx.x;
    const int ty = threadIdx.y;

    const float* __restrict__ ip = in + ((size_t)b * C_CH + c0) * HW + p0;
    #pragma unroll
    for (int k = 0; k < 8; ++k) {
        const int c = ty + 8 * k;
        tile[c][tx] = __ldg(ip + (size_t)c * HW + tx);
    }
    __syncthreads();

    const int tid = ty * 32 + tx;
    const int cl  = tid & 31;            // channel pair
    const int r   = tid >> 5;            // 0..7
    __half2* __restrict__ op =
        (__half2*)(outp + ((size_t)b * HW + p0) * C_CH + c0) + cl;
    #pragma unroll
    for (int m = 0; m < 4; ++m) {
        const int pix = r + 8 * m;
        op[(size_t)pix * (C_CH / 2)] =
            __floats2half2_rn(tile[2 * cl][pix], tile[2 * cl + 1][pix]);
    }
}

// One fp16 tap, HFMA2 accumulate: warp LDG.128 covers all 256 channels.
// p is a pre-scaled uint4-element index (pixel*32).
__device__ __forceinline__ void tap_h(const uint4* __restrict__ T,
                                      int p, __half2 w, int lane,
                                      __half2 a[4])
{
    const uint4 r = __ldg(T + p + lane);
    a[0] = __hfma2(w, *(const __half2*)&r.x, a[0]);
    a[1] = __hfma2(w, *(const __half2*)&r.y, a[1]);
    a[2] = __hfma2(w, *(const __half2*)&r.z, a[2]);
    a[3] = __hfma2(w, *(const __half2*)&r.w, a[3]);
}

__device__ __forceinline__ unsigned int h2_as_u32(__half2 h)
{
    return *(unsigned int*)&h;
}

// -------- main kernel: block = (roi n, row ph), 224 threads = 7 warps --------
// warp w handles pw = w*5 .. w*5+4 (exactly 35); lane owns 8 channels.
__global__ __launch_bounds__(224, 4)
void rroi_main_kernel(const float* __restrict__ rois, float* __restrict__ out)
{
    __shared__ int4  s_pix[ENTRIES];    // 4 tap indices, pre-scaled *32
    __shared__ uint4 s_wt[ENTRIES];     // 4 weights as duplicated half2
    __shared__ float s_out[OUT_W * 257];

    const int n    = blockIdx.x;
    const int ph   = blockIdx.y;
    const int tid  = threadIdx.x;
    const int lane = tid & 31;
    const int wrp  = tid >> 5;

    // ---- Phase 1: descriptors (channel-independent) ----
    const float r1 = __ldg(rois + n * 6 + 1);
    const float r2 = __ldg(rois + n * 6 + 2);
    const float r3 = __ldg(rois + n * 6 + 3);
    const float r4 = __ldg(rois + n * 6 + 4);
    const float r5 = __ldg(rois + n * 6 + 5);
    const int   b  = (int)__ldg(rois + n * 6 + 0);
    float sint, cost;
    sincosf(r5, &sint, &cost);

    for (int e = tid; e < ENTRIES; e += 224) {
        const int pw  = e % OUT_W;
        const int q   = e / OUT_W;
        const int lev = q >> 2;
        const int s   = q & 3;
        const int sy  = s >> 1;
        const int sx  = s & 1;

        const int   Hc = 256 >> lev;
        const int   HW = Hc * Hc;
        const float sc = 0.25f / (float)(1 << lev);

        const float cx = r1 * sc;
        const float cy = r2 * sc;
        const float w  = fmaxf(r3 * sc, 1.0f);
        const float h  = fmaxf(r4 * sc, 1.0f);

        const float gy = (float)ph + ((float)sy + 0.5f) * 0.5f;
        const float gx = (float)pw + ((float)sx + 0.5f) * 0.5f;
        const float yy = gy * (h * (1.0f / OUT_H)) - 0.5f * h;
        const float xx = gx * (w * (1.0f / OUT_W)) - 0.5f * w;

        float x = xx * cost - yy * sint + cx;
        float y = xx * sint + yy * cost + cy;

        const float Hf = (float)Hc;
        const bool valid = (y >= -1.0f) && (y <= Hf) && (x >= -1.0f) && (x <= Hf);
        y = fminf(fmaxf(y, 0.0f), Hf - 1.0f);
        x = fminf(fmaxf(x, 0.0f), Hf - 1.0f);

        const int y0 = (int)floorf(y);
        const int x0 = (int)floorf(x);
        const int y1 = min(y0 + 1, Hc - 1);
        const int x1 = min(x0 + 1, Hc - 1);
        const float ly = y - (float)y0;
        const float lx = x - (float)x0;
        const float hy = 1.0f - ly;
        const float hx = 1.0f - lx;
        const float qv = valid ? 0.25f : 0.0f;

        const int base = b * HW;
        // pre-scale by 32 (uint4 elements per pixel row of 256 fp16 channels)
        s_pix[e] = make_int4((base + y0 * Hc + x0) * 32,
                             (base + y0 * Hc + x1) * 32,
                             (base + y1 * Hc + x0) * 32,
                             (base + y1 * Hc + x1) * 32);
        s_wt[e] = make_uint4(h2_as_u32(__float2half2_rn(hy * hx * qv)),
                             h2_as_u32(__float2half2_rn(hy * lx * qv)),
                             h2_as_u32(__float2half2_rn(ly * hx * qv)),
                             h2_as_u32(__float2half2_rn(ly * lx * qv)));
    }
    __syncthreads();

    const uint4* __restrict__ T0 = (const uint4*)g_h0;
    const uint4* __restrict__ T1 = (const uint4*)g_h1;
    const uint4* __restrict__ T2 = (const uint4*)g_h2;
    const uint4* __restrict__ T3 = (const uint4*)g_h3;

    // ---- Phase 2: gathers ----
    #pragma unroll
    for (int pwi = 0; pwi < 5; ++pwi) {
        const int pw = wrp * 5 + pwi;
        float best[8];
        #pragma unroll
        for (int lev = 0; lev < 4; ++lev) {
            const uint4* __restrict__ T =
                (lev == 0) ? T0 : (lev == 1) ? T1 : (lev == 2) ? T2 : T3;
            float acc[8] = {0.f, 0.f, 0.f, 0.f, 0.f, 0.f, 0.f, 0.f};
            #pragma unroll
            for (int s = 0; s < 4; ++s) {
                const int e = (lev * 4 + s) * OUT_W + pw;
                const int4  p = s_pix[e];
                const uint4 w = s_wt[e];
                __half2 a[4];
                a[0] = __float2half2_rn(0.f); a[1] = a[0];
                a[2] = a[0];                  a[3] = a[0];
                tap_h(T, p.x, *(const __half2*)&w.x, lane, a);
                tap_h(T, p.y, *(const __half2*)&w.y, lane, a);
                tap_h(T, p.z, *(const __half2*)&w.z, lane, a);
                tap_h(T, p.w, *(const __half2*)&w.w, lane, a);
                #pragma unroll
                for (int k = 0; k < 4; ++k) {
                    const float2 f = __half22float2(a[k]);
                    acc[2 * k]     += f.x;
                    acc[2 * k + 1] += f.y;
                }
            }
            #pragma unroll
            for (int j = 0; j < 8; ++j)
                best[j] = (lev == 0) ? acc[j] : fmaxf(best[j], acc[j]);
        }
        #pragma unroll
        for (int j = 0; j < 8; ++j)
            s_out[pw * 257 + lane * 8 + j] = best[j];
    }
    __syncthreads();

    // ---- Phase 3: coalesced output write ----
    float* __restrict__ ob = out + (((size_t)n * C_CH) * OUT_H + ph) * OUT_W;
    for (int idx = tid; idx < C_CH * OUT_W; idx += 224) {
        const int c  = idx / OUT_W;
        const int pw = idx - c * OUT_W;
        ob[(size_t)c * (OUT_H * OUT_W) + pw] = s_out[pw * 257 + c];
    }
}

extern "C" void kernel_launch(void* const* d_in, const int* in_sizes, int n_in,
                              void* d_out, int out_size)
{
    const float* f0   = (const float*)d_in[0];
    const float* f1   = (const float*)d_in[1];
    const float* f2   = (const float*)d_in[2];
    const float* f3   = (const float*)d_in[3];
    const float* rois = (const float*)d_in[4];
    float* out = (float*)d_out;

    const int N = in_sizes[4] / 6;

    dim3 tb(32, 8);
    transpose_kernel<<<dim3(256 * 256 / 32, C_CH / 64, 2), tb>>>(f0, 256 * 256, 0);
    transpose_kernel<<<dim3(128 * 128 / 32, C_CH / 64, 2), tb>>>(f1, 128 * 128, 1);
    transpose_kernel<<<dim3( 64 *  64 / 32, C_CH / 64, 2), tb>>>(f2,  64 *  64, 2);
    transpose_kernel<<<dim3( 32 *  32 / 32, C_CH / 64, 2), tb>>>(f3,  32 *  32, 3);

    rroi_main_kernel<<<dim3(N, OUT_H), 224>>>(rois, out);
}

// round 11
// speedup vs baseline: 5.5803x; 1.0203x over previous
#include <cuda_runtime.h>
#include <cuda_fp16.h>
#include <stdint.h>
#include <math.h>

#define C_CH  256
#define OUT_H 7
#define OUT_W 35
#define ENTRIES (OUT_W * 4 * 4)   // 560 descriptors per (roi, ph)

// -------- channel-last fp16 scratch (static: allocation-free) --------
__device__ __half g_h0[(size_t)2 * 256 * 256 * 256];  // 67MB
__device__ __half g_h1[(size_t)2 * 256 * 128 * 128];  // 16.8MB
__device__ __half g_h2[(size_t)2 * 256 *  64 *  64];  // 4.2MB
__device__ __half g_h3[(size_t)2 * 256 *  32 *  32];  // 1.05MB

// Fused NCHW fp32 -> NHWC fp16 transpose for all 4 levels, 1D grid.
// Per-level blocks: (HW/32) * 4 channel-groups * 2 batches.
#define NB0 16384   // 2048*8
#define NB1 4096    // 512*8
#define NB2 1024    // 128*8
#define NB3 256     // 32*8
__global__ __launch_bounds__(256)
void transpose_all_kernel(const float* __restrict__ f0,
                          const float* __restrict__ f1,
                          const float* __restrict__ f2,
                          const float* __restrict__ f3)
{
    __shared__ float tile[64][33];
    int bid = blockIdx.x;
    int lev, rel;
    if      (bid < NB0)             { lev = 0; rel = bid; }
    else if (bid < NB0 + NB1)       { lev = 1; rel = bid - NB0; }
    else if (bid < NB0 + NB1 + NB2) { lev = 2; rel = bid - NB0 - NB1; }
    else                            { lev = 3; rel = bid - NB0 - NB1 - NB2; }

    const int Hc = 256 >> lev;
    const int HW = Hc * Hc;
    const int pxb = HW / 32;
    const int p0  = (rel % pxb) * 32;
    const int t   = rel / pxb;          // 0..7
    const int c0  = (t & 3) * 64;
    const int b   = t >> 2;

    const float* __restrict__ in = (lev == 0) ? f0 : (lev == 1) ? f1
                                 : (lev == 2) ? f2 : f3;
    __half* __restrict__ outp = (lev == 0) ? g_h0 : (lev == 1) ? g_h1
                              : (lev == 2) ? g_h2 : g_h3;

    const int tx = threadIdx.x;
    const int ty = threadIdx.y;

    const float* __restrict__ ip = in + ((size_t)b * C_CH + c0) * HW + p0;
    #pragma unroll
    for (int k = 0; k < 8; ++k) {
        const int c = ty + 8 * k;
        tile[c][tx] = __ldg(ip + (size_t)c * HW + tx);
    }
    __syncthreads();

    const int tid = ty * 32 + tx;
    const int cl  = tid & 31;            // channel pair
    const int r   = tid >> 5;            // 0..7
    __half2* __restrict__ op =
        (__half2*)(outp + ((size_t)b * HW + p0) * C_CH + c0) + cl;
    #pragma unroll
    for (int m = 0; m < 4; ++m) {
        const int pix = r + 8 * m;
        op[(size_t)pix * (C_CH / 2)] =
            __floats2half2_rn(tile[2 * cl][pix], tile[2 * cl + 1][pix]);
    }
}

__device__ __forceinline__ unsigned int h2_as_u32(__half2 h)
{
    return *(unsigned int*)&h;
}

// One fp16 tap over 128 channels: lane owns 4 ch (uint2 = 8B).
// p is a pre-scaled uint2-element index (pixel*64 + half*32), lane added by caller.
__device__ __forceinline__ void tap2(const uint2* __restrict__ T,
                                     int p, __half2 w, __half2 a[2])
{
    const uint2 r = __ldg(T + p);
    a[0] = __hfma2(w, *(const __half2*)&r.x, a[0]);
    a[1] = __hfma2(w, *(const __half2*)&r.y, a[1]);
}

// -------- main kernel: block = (roi n, channel-half), 224 threads --------
// Loops ph = 0..6 internally -> cross-row L1 reuse of pixel lines.
// warp w handles pw = w*5 .. w*5+4; lane owns 4 channels.
__global__ __launch_bounds__(224, 4)
void rroi_main_kernel(const float* __restrict__ rois, float* __restrict__ out)
{
    __shared__ int4  s_pix[ENTRIES];    // 4 tap indices, pre-scaled uint2 units
    __shared__ uint4 s_wt[ENTRIES];     // 4 weights as duplicated half2
    __shared__ float s_out[OUT_W * 129];

    const int n    = blockIdx.x;
    const int half = blockIdx.y;        // 0 or 1 -> channels half*128..+127
    const int h32  = half * 32;         // uint2 offset of this half within a pixel
    const int tid  = threadIdx.x;
    const int lane = tid & 31;
    const int wrp  = tid >> 5;

    const float r1 = __ldg(rois + n * 6 + 1);
    const float r2 = __ldg(rois + n * 6 + 2);
    const float r3 = __ldg(rois + n * 6 + 3);
    const float r4 = __ldg(rois + n * 6 + 4);
    const float r5 = __ldg(rois + n * 6 + 5);
    const int   b  = (int)__ldg(rois + n * 6 + 0);
    float sint, cost;
    sincosf(r5, &sint, &cost);

    const uint2* __restrict__ T0 = (const uint2*)g_h0;
    const uint2* __restrict__ T1 = (const uint2*)g_h1;
    const uint2* __restrict__ T2 = (const uint2*)g_h2;
    const uint2* __restrict__ T3 = (const uint2*)g_h3;

    for (int ph = 0; ph < OUT_H; ++ph) {
        // ---- Phase 1: descriptors for this ph ----
        for (int e = tid; e < ENTRIES; e += 224) {
            const int pw  = e % OUT_W;
            const int q   = e / OUT_W;
            const int lev = q >> 2;
            const int s   = q & 3;
            const int sy  = s >> 1;
            const int sx  = s & 1;

            const int   Hc = 256 >> lev;
            const int   HW = Hc * Hc;
            const float sc = 0.25f / (float)(1 << lev);

            const float cx = r1 * sc;
            const float cy = r2 * sc;
            const float w  = fmaxf(r3 * sc, 1.0f);
            const float h  = fmaxf(r4 * sc, 1.0f);

            const float gy = (float)ph + ((float)sy + 0.5f) * 0.5f;
            const float gx = (float)pw + ((float)sx + 0.5f) * 0.5f;
            const float yy = gy * (h * (1.0f / OUT_H)) - 0.5f * h;
            const float xx = gx * (w * (1.0f / OUT_W)) - 0.5f * w;

            float x = xx * cost - yy * sint + cx;
            float y = xx * sint + yy * cost + cy;

            const float Hf = (float)Hc;
            const bool valid = (y >= -1.0f) && (y <= Hf) && (x >= -1.0f) && (x <= Hf);
            y = fminf(fmaxf(y, 0.0f), Hf - 1.0f);
            x = fminf(fmaxf(x, 0.0f), Hf - 1.0f);

            const int y0 = (int)floorf(y);
            const int x0 = (int)floorf(x);
            const int y1 = min(y0 + 1, Hc - 1);
            const int x1 = min(x0 + 1, Hc - 1);
            const float ly = y - (float)y0;
            const float lx = x - (float)x0;
            const float hy = 1.0f - ly;
            const float hx = 1.0f - lx;
            const float qv = valid ? 0.25f : 0.0f;

            const int base = b * HW;
            s_pix[e] = make_int4((base + y0 * Hc + x0) * 64 + h32,
                                 (base + y0 * Hc + x1) * 64 + h32,
                                 (base + y1 * Hc + x0) * 64 + h32,
                                 (base + y1 * Hc + x1) * 64 + h32);
            s_wt[e] = make_uint4(h2_as_u32(__float2half2_rn(hy * hx * qv)),
                                 h2_as_u32(__float2half2_rn(hy * lx * qv)),
                                 h2_as_u32(__float2half2_rn(ly * hx * qv)),
                                 h2_as_u32(__float2half2_rn(ly * lx * qv)));
        }
        __syncthreads();

        // ---- Phase 2: gathers ----
        #pragma unroll
        for (int pwi = 0; pwi < 5; ++pwi) {
            const int pw = wrp * 5 + pwi;
            float best[4];
            #pragma unroll
            for (int lev = 0; lev < 4; ++lev) {
                const uint2* __restrict__ T =
                    (lev == 0) ? T0 : (lev == 1) ? T1 : (lev == 2) ? T2 : T3;
                float acc[4] = {0.f, 0.f, 0.f, 0.f};
                #pragma unroll
                for (int s = 0; s < 4; ++s) {
                    const int e = (lev * 4 + s) * OUT_W + pw;
                    const int4  p = s_pix[e];
                    const uint4 w = s_wt[e];
                    __half2 a[2];
                    a[0] = __float2half2_rn(0.f); a[1] = a[0];
                    tap2(T, p.x + lane, *(const __half2*)&w.x, a);
                    tap2(T, p.y + lane, *(const __half2*)&w.y, a);
                    tap2(T, p.z + lane, *(const __half2*)&w.z, a);
                    tap2(T, p.w + lane, *(const __half2*)&w.w, a);
                    #pragma unroll
                    for (int k = 0; k < 2; ++k) {
                        const float2 f = __half22float2(a[k]);
                        acc[2 * k]     += f.x;
                        acc[2 * k + 1] += f.y;
                    }
                }
                #pragma unroll
                for (int j = 0; j < 4; ++j)
                    best[j] = (lev == 0) ? acc[j] : fmaxf(best[j], acc[j]);
            }
            #pragma unroll
            for (int j = 0; j < 4; ++j)
                s_out[pw * 129 + lane * 4 + j] = best[j];
        }
        __syncthreads();

        // ---- Phase 3: coalesced output write for this ph ----
        float* __restrict__ ob =
            out + (((size_t)n * C_CH + half * 128) * OUT_H + ph) * OUT_W;
        for (int idx = tid; idx < 128 * OUT_W; idx += 224) {
            const int c  = idx / OUT_W;
            const int pw = idx - c * OUT_W;
            ob[(size_t)c * (OUT_H * OUT_W) + pw] = s_out[pw * 129 + c];
        }
        // no extra barrier needed: next descriptor build writes s_pix/s_wt,
        // disjoint from s_out reads; gather of next ph is fenced by the
        // post-build __syncthreads().
    }
}

extern "C" void kernel_launch(void* const* d_in, const int* in_sizes, int n_in,
                              void* d_out, int out_size)
{
    const float* f0   = (const float*)d_in[0];
    const float* f1   = (const float*)d_in[1];
    const float* f2   = (const float*)d_in[2];
    const float* f3   = (const float*)d_in[3];
    const float* rois = (const float*)d_in[4];
    float* out = (float*)d_out;

    const int N = in_sizes[4] / 6;

    transpose_all_kernel<<<NB0 + NB1 + NB2 + NB3, dim3(32, 8)>>>(f0, f1, f2, f3);
    rroi_main_kernel<<<dim3(N, 2), 224>>>(rois, out);
}